// round 13
// baseline (speedup 1.0000x reference)
#include <cuda_runtime.h>
#include <cstdint>

#define B_ROWS 16384
#define IN_DIM 1024
#define H_DIM  2048
#define K_TOP  256
#define NC_DIM 1000

// ---------------- scratch (__device__ globals; no cudaMalloc) ----------------
__device__ float g_f[(size_t)B_ROWS * H_DIM];       // dense fp32 activations
__device__ float g_w1t[(size_t)H_DIM * H_DIM];      // W1^T  [k][n]
__device__ float g_wct[(size_t)H_DIM * NC_DIM];     // Wc^T  [k][n]
__device__ int2  g_cp[(size_t)B_ROWS * K_TOP];      // compact (valbits, idx)
__device__ short g_bnd[(size_t)B_ROWS * 8];         // per-row k-phase segment starts (8 phases)

// ================= f32x2 helpers (proven) =================
__device__ __forceinline__ unsigned long long dup2(float x) {
    unsigned long long r; unsigned b = __float_as_uint(x);
    asm("mov.b64 %0, {%1, %2};" : "=l"(r) : "r"(b), "r"(b));
    return r;
}
__device__ __forceinline__ void fma2(unsigned long long& d,
                                     unsigned long long a,
                                     unsigned long long b) {
    asm("fma.rn.f32x2 %0, %1, %2, %0;" : "+l"(d) : "l"(a), "l"(b));
}
__device__ __forceinline__ void unpack2(unsigned long long p, float& lo, float& hi) {
    unsigned l, h;
    asm("mov.b64 {%0, %1}, %2;" : "=r"(l), "=r"(h) : "l"(p));
    lo = __uint_as_float(l); hi = __uint_as_float(h);
}

// ================= PROVEN dense f32x2 GEMM (round-3, verbatim) =================
__global__ __launch_bounds__(256, 2)
void gemm_nt_kernel(const float* __restrict__ A, const float* __restrict__ W,
                    const float* __restrict__ bias, float* __restrict__ C,
                    int N, int Kd)
{
    __shared__ float As[2][16][132];
    __shared__ float Bs[2][16][132];

    const int tid = threadIdx.x;
    const int tx = tid & 15;
    const int ty = tid >> 4;
    const int m0 = blockIdx.y * 128;
    const int n0 = blockIdx.x * 128;

    const int lrow = tid >> 2;
    const int lc4  = tid & 3;
    const size_t aBase0 = (size_t)(m0 + lrow)      * Kd + lc4 * 4;
    const size_t aBase1 = (size_t)(m0 + lrow + 64) * Kd + lc4 * 4;
    const size_t bBase0 = (size_t)(n0 + lrow)      * Kd + lc4 * 4;
    const size_t bBase1 = (size_t)(n0 + lrow + 64) * Kd + lc4 * 4;

    unsigned long long acc[8][4];
    #pragma unroll
    for (int i = 0; i < 8; ++i)
        #pragma unroll
        for (int j = 0; j < 4; ++j) acc[i][j] = 0ULL;

    const int nkt = Kd >> 4;

    float4 ra0 = *(const float4*)(A + aBase0);
    float4 ra1 = *(const float4*)(A + aBase1);
    float4 rb0 = *(const float4*)(W + bBase0);
    float4 rb1 = *(const float4*)(W + bBase1);

    {
        const int kb = lc4 * 4;
        As[0][kb+0][lrow] = ra0.x; As[0][kb+1][lrow] = ra0.y;
        As[0][kb+2][lrow] = ra0.z; As[0][kb+3][lrow] = ra0.w;
        As[0][kb+0][lrow+64] = ra1.x; As[0][kb+1][lrow+64] = ra1.y;
        As[0][kb+2][lrow+64] = ra1.z; As[0][kb+3][lrow+64] = ra1.w;
        Bs[0][kb+0][lrow] = rb0.x; Bs[0][kb+1][lrow] = rb0.y;
        Bs[0][kb+2][lrow] = rb0.z; Bs[0][kb+3][lrow] = rb0.w;
        Bs[0][kb+0][lrow+64] = rb1.x; Bs[0][kb+1][lrow+64] = rb1.y;
        Bs[0][kb+2][lrow+64] = rb1.z; Bs[0][kb+3][lrow+64] = rb1.w;
    }
    __syncthreads();

    for (int kt = 0; kt < nkt; ++kt) {
        const int cur = kt & 1, nxt = cur ^ 1;
        float4 na0, na1, nb0, nb1;
        const bool more = (kt + 1) < nkt;
        if (more) {
            const size_t koff = (size_t)(kt + 1) * 16;
            na0 = *(const float4*)(A + aBase0 + koff);
            na1 = *(const float4*)(A + aBase1 + koff);
            nb0 = *(const float4*)(W + bBase0 + koff);
            nb1 = *(const float4*)(W + bBase1 + koff);
        }

        #pragma unroll
        for (int kk = 0; kk < 16; ++kk) {
            const float4 av0 = *(const float4*)&As[cur][kk][ty * 8];
            const float4 av1 = *(const float4*)&As[cur][kk][ty * 8 + 4];
            const ulonglong2 bl = *(const ulonglong2*)&Bs[cur][kk][tx * 8];
            const ulonglong2 bh = *(const ulonglong2*)&Bs[cur][kk][tx * 8 + 4];
            unsigned long long bb0 = bl.x, bb1 = bl.y, bb2 = bh.x, bb3 = bh.y;
            unsigned long long aa[8];
            aa[0] = dup2(av0.x); aa[1] = dup2(av0.y);
            aa[2] = dup2(av0.z); aa[3] = dup2(av0.w);
            aa[4] = dup2(av1.x); aa[5] = dup2(av1.y);
            aa[6] = dup2(av1.z); aa[7] = dup2(av1.w);
            #pragma unroll
            for (int i = 0; i < 8; ++i) {
                fma2(acc[i][0], aa[i], bb0);
                fma2(acc[i][1], aa[i], bb1);
                fma2(acc[i][2], aa[i], bb2);
                fma2(acc[i][3], aa[i], bb3);
            }
        }

        if (more) {
            const int kb = lc4 * 4;
            As[nxt][kb+0][lrow] = na0.x; As[nxt][kb+1][lrow] = na0.y;
            As[nxt][kb+2][lrow] = na0.z; As[nxt][kb+3][lrow] = na0.w;
            As[nxt][kb+0][lrow+64] = na1.x; As[nxt][kb+1][lrow+64] = na1.y;
            As[nxt][kb+2][lrow+64] = na1.z; As[nxt][kb+3][lrow+64] = na1.w;
            Bs[nxt][kb+0][lrow] = nb0.x; Bs[nxt][kb+1][lrow] = nb0.y;
            Bs[nxt][kb+2][lrow] = nb0.z; Bs[nxt][kb+3][lrow] = nb0.w;
            Bs[nxt][kb+0][lrow+64] = nb1.x; Bs[nxt][kb+1][lrow+64] = nb1.y;
            Bs[nxt][kb+2][lrow+64] = nb1.z; Bs[nxt][kb+3][lrow+64] = nb1.w;
        }
        __syncthreads();
    }

    #pragma unroll
    for (int i = 0; i < 8; ++i) {
        const int m = m0 + ty * 8 + i;
        float* crow = C + (size_t)m * N;
        #pragma unroll
        for (int j = 0; j < 4; ++j) {
            float lo, hi;
            unpack2(acc[i][j], lo, hi);
            const int n = n0 + tx * 8 + j * 2;
            crow[n]     = lo + bias[n];
            crow[n + 1] = hi + bias[n + 1];
        }
    }
}

// ===== top-K + ReLU -> compact (val,idx) pairs + 8-phase boundary table =====
__global__ __launch_bounds__(256)
void topk_relu_compact_kernel(const float* __restrict__ buf,
                              int2* __restrict__ cp, short* __restrict__ bnd)
{
    __shared__ unsigned s_hist[256];
    __shared__ unsigned s_scan[2][256];
    __shared__ unsigned s_bin, s_k;

    const int tid = threadIdx.x;
    const size_t base = (size_t)blockIdx.x * H_DIM;

    float v[8]; unsigned u[8];
    {
        const float4 f0 = *(const float4*)(buf + base + tid * 8);
        const float4 f1 = *(const float4*)(buf + base + tid * 8 + 4);
        v[0]=f0.x; v[1]=f0.y; v[2]=f0.z; v[3]=f0.w;
        v[4]=f1.x; v[5]=f1.y; v[6]=f1.z; v[7]=f1.w;
    }
    #pragma unroll
    for (int s = 0; s < 8; ++s) {
        const unsigned bits = __float_as_uint(v[s]);
        u[s] = bits ^ ((bits & 0x80000000u) ? 0xFFFFFFFFu : 0x80000000u);
    }

    unsigned prefHi = 0;
    unsigned kneed = K_TOP;

    #pragma unroll
    for (int level = 3; level >= 0; --level) {
        s_hist[tid] = 0;
        __syncthreads();
        #pragma unroll
        for (int s = 0; s < 8; ++s) {
            const unsigned hiBits = (level == 3) ? 0u : (u[s] >> ((level + 1) * 8));
            if (level == 3 || hiBits == prefHi)
                atomicAdd(&s_hist[(u[s] >> (level * 8)) & 255u], 1u);
        }
        __syncthreads();
        unsigned val = s_hist[tid];
        s_scan[0][tid] = val;
        __syncthreads();
        int src = 0;
        #pragma unroll
        for (int d = 1; d < 256; d <<= 1) {
            if (tid + d < 256) val += s_scan[src][tid + d];
            s_scan[src ^ 1][tid] = val;
            __syncthreads();
            src ^= 1;
        }
        const unsigned above = (tid < 255) ? s_scan[src][tid + 1] : 0u;
        if (val >= kneed && above < kneed) { s_bin = (unsigned)tid; s_k = kneed - above; }
        __syncthreads();
        prefHi = (prefHi << 8) | s_bin;
        kneed = s_k;
        __syncthreads();
    }

    const unsigned T = prefHi;
    const unsigned r = kneed;

    unsigned myEq = 0;
    #pragma unroll
    for (int s = 0; s < 8; ++s) myEq += (u[s] == T) ? 1u : 0u;
    unsigned pval = myEq;
    s_scan[0][tid] = pval;
    __syncthreads();
    int src = 0;
    #pragma unroll
    for (int d = 1; d < 256; d <<= 1) {
        if (tid >= d) pval += s_scan[src][tid - d];
        s_scan[src ^ 1][tid] = pval;
        __syncthreads();
        src ^= 1;
    }
    unsigned rank = pval - myEq;

    int kflag = 0; unsigned myKeep = 0;
    #pragma unroll
    for (int s = 0; s < 8; ++s) {
        bool keep;
        if (u[s] > T)       keep = true;
        else if (u[s] == T) { keep = (rank < r); ++rank; }
        else                keep = false;
        if (keep) { kflag |= (1 << s); ++myKeep; }
    }

    __syncthreads();
    unsigned p2 = myKeep;
    s_scan[0][tid] = p2;
    __syncthreads();
    src = 0;
    #pragma unroll
    for (int d = 1; d < 256; d <<= 1) {
        if (tid >= d) p2 += s_scan[src][tid - d];
        s_scan[src ^ 1][tid] = p2;
        __syncthreads();
        src ^= 1;
    }
    unsigned pos = p2 - myKeep;        // exclusive prefix of keeps

    // 8 k-phase boundaries: phase p (k in [256p,256p+256)) starts at tid 32p
    if ((tid & 31) == 0) bnd[(size_t)blockIdx.x * 8 + (tid >> 5)] = (short)pos;

    int2* cprow = cp + (size_t)blockIdx.x * K_TOP;
    #pragma unroll
    for (int s = 0; s < 8; ++s) {
        if (kflag & (1 << s)) {
            int2 e;
            e.x = __float_as_int(fmaxf(v[s], 0.0f));
            e.y = tid * 8 + s;
            cprow[pos] = e;
            ++pos;
        }
    }
}

// ================= transpose: src[R][C] -> dst[C][R] =================
__global__ __launch_bounds__(256)
void transpose_kernel(const float* __restrict__ src, float* __restrict__ dst,
                      int R, int Ccols)
{
    __shared__ float t[32][33];
    const int c0 = blockIdx.x * 32, r0 = blockIdx.y * 32;
    for (int i = threadIdx.y; i < 32; i += 8) {
        const int rr = r0 + i, cc = c0 + threadIdx.x;
        t[i][threadIdx.x] = (rr < R && cc < Ccols) ? src[(size_t)rr * Ccols + cc] : 0.f;
    }
    __syncthreads();
    for (int i = threadIdx.y; i < 32; i += 8) {
        const int cc = c0 + i, rr = r0 + threadIdx.x;
        if (cc < Ccols && rr < R) dst[(size_t)cc * R + rr] = t[threadIdx.x][i];
    }
}

// ===== sparse GEMM v4: NT=64 (LDS.64, acc 16 regs) -> 8-wide MLP batches, KP=256 =====
#define NT 64
#define KP 256
#define NPH (H_DIM / KP)               // 8
#define SLAB4_BYTES (KP * NT * 4)      // 65536

template<bool BOUND_N>
__global__ __launch_bounds__(256, 2)
void sparse_gemm4_kernel(const int2* __restrict__ cp, const short* __restrict__ bnd,
                         const float* __restrict__ Wt, const float* __restrict__ bias,
                         float* __restrict__ C, int N)
{
    extern __shared__ float slab[];
    const int tid = threadIdx.x;
    const int wid = tid >> 5, lane = tid & 31;
    const int n0 = blockIdx.x * NT;
    const int m0 = blockIdx.y * 128;           // 128 rows/CTA, 16 per warp
    const int nl = n0 + lane * 2;
    const float* slabL = slab + lane * 2;      // per-lane col base

    unsigned long long acc[16];                // 2 cols per row
    #pragma unroll
    for (int rr = 0; rr < 16; ++rr) acc[rr] = 0ULL;

    for (int p = 0; p < NPH; ++p) {
        const int kp0 = p * KP;
        __syncthreads();
        // stage slab: Wt[kp0+k][n0+c] -> slab[k*64 + c]; 4096 float4 slots, 16/thread
        #pragma unroll 4
        for (int idx = tid; idx < KP * 16; idx += 256) {
            const int k = idx >> 4, cg = (idx & 15) * 4;
            float4 w;
            if (!BOUND_N || (n0 + cg + 4) <= N)
                w = *(const float4*)(Wt + (size_t)(kp0 + k) * N + n0 + cg);
            else {
                w = make_float4(0.f, 0.f, 0.f, 0.f);
                #pragma unroll
                for (int i = 0; i < 4; ++i)
                    if (n0 + cg + i < N) ((float*)&w)[i] = Wt[(size_t)(kp0 + k) * N + n0 + cg + i];
            }
            *(float4*)(slab + k * NT + cg) = w;
        }
        __syncthreads();

        #pragma unroll
        for (int rr = 0; rr < 16; ++rr) {
            const int row = m0 + wid * 16 + rr;
            const int b0 = bnd[(size_t)row * 8 + p];
            const int b1 = (p == NPH - 1) ? K_TOP : (int)bnd[(size_t)row * 8 + p + 1];
            const int2* rowcp = cp + (size_t)row * K_TOP;
            int j = b0;
            while (j < b1) {
                const int cb = j & ~31;
                const int2 c = rowcp[cb + lane];       // coalesced chunk preload
                const int je = min(b1, cb + 32);
                // 8-wide batches: 8 independent LDS.64 chains
                for (; j + 7 < je; j += 8) {
                    const int s = j - cb;
                    float a[8]; int kk[8];
                    #pragma unroll
                    for (int q = 0; q < 8; ++q) {
                        a[q]  = __int_as_float(__shfl_sync(0xFFFFFFFFu, c.x, s + q));
                        kk[q] = __shfl_sync(0xFFFFFFFFu, c.y, s + q) - kp0;
                    }
                    unsigned long long w[8];
                    #pragma unroll
                    for (int q = 0; q < 8; ++q)
                        w[q] = *(const unsigned long long*)(slabL + (kk[q] << 6));
                    #pragma unroll
                    for (int q = 0; q < 8; ++q)
                        fma2(acc[rr], dup2(a[q]), w[q]);
                }
                for (; j < je; ++j) {
                    const int s = j - cb;
                    const float a = __int_as_float(__shfl_sync(0xFFFFFFFFu, c.x, s));
                    const int k = __shfl_sync(0xFFFFFFFFu, c.y, s) - kp0;
                    const unsigned long long w = *(const unsigned long long*)(slabL + (k << 6));
                    fma2(acc[rr], dup2(a), w);
                }
            }
        }
    }

    // epilogue
    #pragma unroll
    for (int rr = 0; rr < 16; ++rr) {
        const int row = m0 + wid * 16 + rr;
        float v0, v1;
        unpack2(acc[rr], v0, v1);
        if (!BOUND_N || nl + 2 <= N) {
            const float2 bv = *(const float2*)(bias + nl);
            *(float2*)(C + (size_t)row * N + nl) = make_float2(v0 + bv.x, v1 + bv.y);
        } else {
            if (nl < N)     C[(size_t)row * N + nl]     = v0 + bias[nl];
            if (nl + 1 < N) C[(size_t)row * N + nl + 1] = v1 + bias[nl + 1];
        }
    }
}

// ================= launch =================
extern "C" void kernel_launch(void* const* d_in, const int* in_sizes, int n_in,
                              void* d_out, int out_size)
{
    const float* x  = (const float*)d_in[0];
    const float* W0 = (const float*)d_in[1];
    const float* b0 = (const float*)d_in[2];
    const float* W1 = (const float*)d_in[3];
    const float* b1 = (const float*)d_in[4];
    const float* Wc = (const float*)d_in[5];
    const float* bc = (const float*)d_in[6];
    float* out = (float*)d_out;

    float *f, *w1t, *wct;
    int2* cp;
    short* bnd;
    cudaGetSymbolAddress((void**)&f,   g_f);
    cudaGetSymbolAddress((void**)&w1t, g_w1t);
    cudaGetSymbolAddress((void**)&wct, g_wct);
    cudaGetSymbolAddress((void**)&cp,  g_cp);
    cudaGetSymbolAddress((void**)&bnd, g_bnd);

    cudaFuncSetAttribute(sparse_gemm4_kernel<false>,
                         cudaFuncAttributeMaxDynamicSharedMemorySize, SLAB4_BYTES);
    cudaFuncSetAttribute(sparse_gemm4_kernel<true>,
                         cudaFuncAttributeMaxDynamicSharedMemorySize, SLAB4_BYTES);

    const dim3 blk(256);

    // weight transposes
    transpose_kernel<<<dim3(H_DIM / 32, H_DIM / 32), dim3(32, 8)>>>(W1, w1t, H_DIM, H_DIM);
    transpose_kernel<<<dim3(H_DIM / 32, (NC_DIM + 31) / 32), dim3(32, 8)>>>(Wc, wct, NC_DIM, H_DIM);

    // Layer 0 (dense, proven)
    gemm_nt_kernel<<<dim3(H_DIM / 128, B_ROWS / 128), blk>>>(x, W0, b0, f, H_DIM, IN_DIM);
    topk_relu_compact_kernel<<<B_ROWS, blk>>>(f, cp, bnd);

    // Layer 1 (sparse v4)
    sparse_gemm4_kernel<false><<<dim3(H_DIM / NT, B_ROWS / 128), blk, SLAB4_BYTES>>>(
        cp, bnd, w1t, b1, f, H_DIM);
    topk_relu_compact_kernel<<<B_ROWS, blk>>>(f, cp, bnd);

    // Classifier (sparse v4, N=1000)
    sparse_gemm4_kernel<true><<<dim3((NC_DIM + NT - 1) / NT, B_ROWS / 128), blk, SLAB4_BYTES>>>(
        cp, bnd, wct, bc, out, NC_DIM);
}

// round 14
// speedup vs baseline: 1.2565x; 1.2565x over previous
#include <cuda_runtime.h>
#include <cstdint>

#define B_ROWS 16384
#define IN_DIM 1024
#define H_DIM  2048
#define K_TOP  256
#define NC_DIM 1000

// ---------------- scratch (__device__ globals; no cudaMalloc) ----------------
__device__ float g_f[(size_t)B_ROWS * H_DIM];       // dense fp32 activations
__device__ float g_w1t[(size_t)H_DIM * H_DIM];      // W1^T  [k][n]
__device__ float g_wct[(size_t)H_DIM * NC_DIM];     // Wc^T  [k][n]
__device__ int2  g_cp[(size_t)B_ROWS * K_TOP];      // compact (valbits, idx)
__device__ short g_bnd[(size_t)B_ROWS * 16];        // per-row k-phase segment starts (16 phases)

// ================= f32x2 helpers (proven) =================
__device__ __forceinline__ unsigned long long dup2(float x) {
    unsigned long long r; unsigned b = __float_as_uint(x);
    asm("mov.b64 %0, {%1, %2};" : "=l"(r) : "r"(b), "r"(b));
    return r;
}
__device__ __forceinline__ void fma2(unsigned long long& d,
                                     unsigned long long a,
                                     unsigned long long b) {
    asm("fma.rn.f32x2 %0, %1, %2, %0;" : "+l"(d) : "l"(a), "l"(b));
}
__device__ __forceinline__ void unpack2(unsigned long long p, float& lo, float& hi) {
    unsigned l, h;
    asm("mov.b64 {%0, %1}, %2;" : "=r"(l), "=r"(h) : "l"(p));
    lo = __uint_as_float(l); hi = __uint_as_float(h);
}

// ================= PROVEN dense f32x2 GEMM (round-3, verbatim) =================
__global__ __launch_bounds__(256, 2)
void gemm_nt_kernel(const float* __restrict__ A, const float* __restrict__ W,
                    const float* __restrict__ bias, float* __restrict__ C,
                    int N, int Kd)
{
    __shared__ float As[2][16][132];
    __shared__ float Bs[2][16][132];

    const int tid = threadIdx.x;
    const int tx = tid & 15;
    const int ty = tid >> 4;
    const int m0 = blockIdx.y * 128;
    const int n0 = blockIdx.x * 128;

    const int lrow = tid >> 2;
    const int lc4  = tid & 3;
    const size_t aBase0 = (size_t)(m0 + lrow)      * Kd + lc4 * 4;
    const size_t aBase1 = (size_t)(m0 + lrow + 64) * Kd + lc4 * 4;
    const size_t bBase0 = (size_t)(n0 + lrow)      * Kd + lc4 * 4;
    const size_t bBase1 = (size_t)(n0 + lrow + 64) * Kd + lc4 * 4;

    unsigned long long acc[8][4];
    #pragma unroll
    for (int i = 0; i < 8; ++i)
        #pragma unroll
        for (int j = 0; j < 4; ++j) acc[i][j] = 0ULL;

    const int nkt = Kd >> 4;

    float4 ra0 = *(const float4*)(A + aBase0);
    float4 ra1 = *(const float4*)(A + aBase1);
    float4 rb0 = *(const float4*)(W + bBase0);
    float4 rb1 = *(const float4*)(W + bBase1);

    {
        const int kb = lc4 * 4;
        As[0][kb+0][lrow] = ra0.x; As[0][kb+1][lrow] = ra0.y;
        As[0][kb+2][lrow] = ra0.z; As[0][kb+3][lrow] = ra0.w;
        As[0][kb+0][lrow+64] = ra1.x; As[0][kb+1][lrow+64] = ra1.y;
        As[0][kb+2][lrow+64] = ra1.z; As[0][kb+3][lrow+64] = ra1.w;
        Bs[0][kb+0][lrow] = rb0.x; Bs[0][kb+1][lrow] = rb0.y;
        Bs[0][kb+2][lrow] = rb0.z; Bs[0][kb+3][lrow] = rb0.w;
        Bs[0][kb+0][lrow+64] = rb1.x; Bs[0][kb+1][lrow+64] = rb1.y;
        Bs[0][kb+2][lrow+64] = rb1.z; Bs[0][kb+3][lrow+64] = rb1.w;
    }
    __syncthreads();

    for (int kt = 0; kt < nkt; ++kt) {
        const int cur = kt & 1, nxt = cur ^ 1;
        float4 na0, na1, nb0, nb1;
        const bool more = (kt + 1) < nkt;
        if (more) {
            const size_t koff = (size_t)(kt + 1) * 16;
            na0 = *(const float4*)(A + aBase0 + koff);
            na1 = *(const float4*)(A + aBase1 + koff);
            nb0 = *(const float4*)(W + bBase0 + koff);
            nb1 = *(const float4*)(W + bBase1 + koff);
        }

        #pragma unroll
        for (int kk = 0; kk < 16; ++kk) {
            const float4 av0 = *(const float4*)&As[cur][kk][ty * 8];
            const float4 av1 = *(const float4*)&As[cur][kk][ty * 8 + 4];
            const ulonglong2 bl = *(const ulonglong2*)&Bs[cur][kk][tx * 8];
            const ulonglong2 bh = *(const ulonglong2*)&Bs[cur][kk][tx * 8 + 4];
            unsigned long long bb0 = bl.x, bb1 = bl.y, bb2 = bh.x, bb3 = bh.y;
            unsigned long long aa[8];
            aa[0] = dup2(av0.x); aa[1] = dup2(av0.y);
            aa[2] = dup2(av0.z); aa[3] = dup2(av0.w);
            aa[4] = dup2(av1.x); aa[5] = dup2(av1.y);
            aa[6] = dup2(av1.z); aa[7] = dup2(av1.w);
            #pragma unroll
            for (int i = 0; i < 8; ++i) {
                fma2(acc[i][0], aa[i], bb0);
                fma2(acc[i][1], aa[i], bb1);
                fma2(acc[i][2], aa[i], bb2);
                fma2(acc[i][3], aa[i], bb3);
            }
        }

        if (more) {
            const int kb = lc4 * 4;
            As[nxt][kb+0][lrow] = na0.x; As[nxt][kb+1][lrow] = na0.y;
            As[nxt][kb+2][lrow] = na0.z; As[nxt][kb+3][lrow] = na0.w;
            As[nxt][kb+0][lrow+64] = na1.x; As[nxt][kb+1][lrow+64] = na1.y;
            As[nxt][kb+2][lrow+64] = na1.z; As[nxt][kb+3][lrow+64] = na1.w;
            Bs[nxt][kb+0][lrow] = nb0.x; Bs[nxt][kb+1][lrow] = nb0.y;
            Bs[nxt][kb+2][lrow] = nb0.z; Bs[nxt][kb+3][lrow] = nb0.w;
            Bs[nxt][kb+0][lrow+64] = nb1.x; Bs[nxt][kb+1][lrow+64] = nb1.y;
            Bs[nxt][kb+2][lrow+64] = nb1.z; Bs[nxt][kb+3][lrow+64] = nb1.w;
        }
        __syncthreads();
    }

    #pragma unroll
    for (int i = 0; i < 8; ++i) {
        const int m = m0 + ty * 8 + i;
        float* crow = C + (size_t)m * N;
        #pragma unroll
        for (int j = 0; j < 4; ++j) {
            float lo, hi;
            unpack2(acc[i][j], lo, hi);
            const int n = n0 + tx * 8 + j * 2;
            crow[n]     = lo + bias[n];
            crow[n + 1] = hi + bias[n + 1];
        }
    }
}

// ===== top-K + ReLU -> compact (val,idx) pairs + 16-phase boundary table =====
__global__ __launch_bounds__(256)
void topk_relu_compact_kernel(const float* __restrict__ buf,
                              int2* __restrict__ cp, short* __restrict__ bnd)
{
    __shared__ unsigned s_hist[256];
    __shared__ unsigned s_scan[2][256];
    __shared__ unsigned s_bin, s_k;

    const int tid = threadIdx.x;
    const size_t base = (size_t)blockIdx.x * H_DIM;

    float v[8]; unsigned u[8];
    {
        const float4 f0 = *(const float4*)(buf + base + tid * 8);
        const float4 f1 = *(const float4*)(buf + base + tid * 8 + 4);
        v[0]=f0.x; v[1]=f0.y; v[2]=f0.z; v[3]=f0.w;
        v[4]=f1.x; v[5]=f1.y; v[6]=f1.z; v[7]=f1.w;
    }
    #pragma unroll
    for (int s = 0; s < 8; ++s) {
        const unsigned bits = __float_as_uint(v[s]);
        u[s] = bits ^ ((bits & 0x80000000u) ? 0xFFFFFFFFu : 0x80000000u);
    }

    unsigned prefHi = 0;
    unsigned kneed = K_TOP;

    #pragma unroll
    for (int level = 3; level >= 0; --level) {
        s_hist[tid] = 0;
        __syncthreads();
        #pragma unroll
        for (int s = 0; s < 8; ++s) {
            const unsigned hiBits = (level == 3) ? 0u : (u[s] >> ((level + 1) * 8));
            if (level == 3 || hiBits == prefHi)
                atomicAdd(&s_hist[(u[s] >> (level * 8)) & 255u], 1u);
        }
        __syncthreads();
        unsigned val = s_hist[tid];
        s_scan[0][tid] = val;
        __syncthreads();
        int src = 0;
        #pragma unroll
        for (int d = 1; d < 256; d <<= 1) {
            if (tid + d < 256) val += s_scan[src][tid + d];
            s_scan[src ^ 1][tid] = val;
            __syncthreads();
            src ^= 1;
        }
        const unsigned above = (tid < 255) ? s_scan[src][tid + 1] : 0u;
        if (val >= kneed && above < kneed) { s_bin = (unsigned)tid; s_k = kneed - above; }
        __syncthreads();
        prefHi = (prefHi << 8) | s_bin;
        kneed = s_k;
        __syncthreads();
    }

    const unsigned T = prefHi;
    const unsigned r = kneed;

    unsigned myEq = 0;
    #pragma unroll
    for (int s = 0; s < 8; ++s) myEq += (u[s] == T) ? 1u : 0u;
    unsigned pval = myEq;
    s_scan[0][tid] = pval;
    __syncthreads();
    int src = 0;
    #pragma unroll
    for (int d = 1; d < 256; d <<= 1) {
        if (tid >= d) pval += s_scan[src][tid - d];
        s_scan[src ^ 1][tid] = pval;
        __syncthreads();
        src ^= 1;
    }
    unsigned rank = pval - myEq;

    int kflag = 0; unsigned myKeep = 0;
    #pragma unroll
    for (int s = 0; s < 8; ++s) {
        bool keep;
        if (u[s] > T)       keep = true;
        else if (u[s] == T) { keep = (rank < r); ++rank; }
        else                keep = false;
        if (keep) { kflag |= (1 << s); ++myKeep; }
    }

    __syncthreads();
    unsigned p2 = myKeep;
    s_scan[0][tid] = p2;
    __syncthreads();
    src = 0;
    #pragma unroll
    for (int d = 1; d < 256; d <<= 1) {
        if (tid >= d) p2 += s_scan[src][tid - d];
        s_scan[src ^ 1][tid] = p2;
        __syncthreads();
        src ^= 1;
    }
    unsigned pos = p2 - myKeep;        // exclusive prefix of keeps

    // 16 k-phase boundaries: phase p (k in [128p,128p+128)) starts at tid 16p
    if ((tid & 15) == 0) bnd[(size_t)blockIdx.x * 16 + (tid >> 4)] = (short)pos;

    int2* cprow = cp + (size_t)blockIdx.x * K_TOP;
    #pragma unroll
    for (int s = 0; s < 8; ++s) {
        if (kflag & (1 << s)) {
            int2 e;
            e.x = __float_as_int(fmaxf(v[s], 0.0f));
            e.y = tid * 8 + s;
            cprow[pos] = e;
            ++pos;
        }
    }
}

// ================= transpose: src[R][C] -> dst[C][R] =================
__global__ __launch_bounds__(256)
void transpose_kernel(const float* __restrict__ src, float* __restrict__ dst,
                      int R, int Ccols)
{
    __shared__ float t[32][33];
    const int c0 = blockIdx.x * 32, r0 = blockIdx.y * 32;
    for (int i = threadIdx.y; i < 32; i += 8) {
        const int rr = r0 + i, cc = c0 + threadIdx.x;
        t[i][threadIdx.x] = (rr < R && cc < Ccols) ? src[(size_t)rr * Ccols + cc] : 0.f;
    }
    __syncthreads();
    for (int i = threadIdx.y; i < 32; i += 8) {
        const int cc = c0 + i, rr = r0 + threadIdx.x;
        if (cc < Ccols && rr < R) dst[(size_t)cc * R + rr] = t[threadIdx.x][i];
    }
}

// ===== sparse GEMM v5: v3 inner loop, 8 rows/warp (occ 3), row-ahead chunk prefetch =====
#define NT 128
#define KP 128
#define NPH (H_DIM / KP)               // 16
#define SLAB5_BYTES (KP * NT * 4)      // 65536

template<bool BOUND_N>
__global__ __launch_bounds__(256, 3)
void sparse_gemm5_kernel(const int2* __restrict__ cp, const short* __restrict__ bnd,
                         const float* __restrict__ Wt, const float* __restrict__ bias,
                         float* __restrict__ C, int N)
{
    extern __shared__ float slab[];
    const int tid = threadIdx.x;
    const int wid = tid >> 5, lane = tid & 31;
    const int n0 = blockIdx.x * NT;
    const int m0 = blockIdx.y * 64;          // 64 rows/CTA, 8 per warp
    const int nl = n0 + lane * 4;

    unsigned long long acc0[8], acc1[8];     // cols nl..nl+1, nl+2..nl+3
    #pragma unroll
    for (int rr = 0; rr < 8; ++rr) { acc0[rr] = 0ULL; acc1[rr] = 0ULL; }

    const int row0 = m0 + wid * 8;

    for (int p = 0; p < NPH; ++p) {
        const int kp0 = p * KP;
        __syncthreads();
        // stage slab: Wt[kp0+k][n0+c]; KP*32 float4 slots, 16 per thread
        #pragma unroll 4
        for (int idx = tid; idx < KP * 32; idx += 256) {
            const int k = idx >> 5, cg = (idx & 31) * 4;
            float4 w;
            if (!BOUND_N || (n0 + cg + 4) <= N)
                w = *(const float4*)(Wt + (size_t)(kp0 + k) * N + n0 + cg);
            else {
                w = make_float4(0.f, 0.f, 0.f, 0.f);
                #pragma unroll
                for (int i = 0; i < 4; ++i)
                    if (n0 + cg + i < N) ((float*)&w)[i] = Wt[(size_t)(kp0 + k) * N + n0 + cg + i];
            }
            *(float4*)(slab + k * NT + cg) = w;
        }
        __syncthreads();

        // lane-parallel per-row bounds (8 rows per warp)
        int b0v = 0, b1v = 0;
        if (lane < 8) {
            b0v = bnd[(size_t)(row0 + lane) * 16 + p];
            b1v = (p == NPH - 1) ? K_TOP : (int)bnd[(size_t)(row0 + lane) * 16 + p + 1];
        }

        // prefetch row 0's first chunk
        int b0c = __shfl_sync(0xFFFFFFFFu, b0v, 0);
        int b1c = __shfl_sync(0xFFFFFFFFu, b1v, 0);
        int2 cc = cp[(size_t)row0 * K_TOP + (b0c & ~31) + lane];

        #pragma unroll
        for (int rr = 0; rr < 8; ++rr) {
            // prefetch next row's bounds + first chunk (hides the ~240cyc LDG)
            int b0n = 0, b1n = 0; int2 cn = cc;
            if (rr < 7) {
                b0n = __shfl_sync(0xFFFFFFFFu, b0v, rr + 1);
                b1n = __shfl_sync(0xFFFFFFFFu, b1v, rr + 1);
                cn = cp[(size_t)(row0 + rr + 1) * K_TOP + (b0n & ~31) + lane];
            }

            const int2* rowcp = cp + (size_t)(row0 + rr) * K_TOP;
            int j = b0c;
            int cb = b0c & ~31;
            int2 c = cc;
            while (j < b1c) {
                if ((j & ~31) != cb) { cb = j & ~31; c = rowcp[cb + lane]; }
                const int je = min(b1c, cb + 32);
                // 4-wide batches: MLP across shfl/LDS chains (v3 body)
                for (; j + 3 < je; j += 4) {
                    const int s = j - cb;
                    const unsigned long long a0 = dup2(__int_as_float(__shfl_sync(0xFFFFFFFFu, c.x, s)));
                    const unsigned long long a1 = dup2(__int_as_float(__shfl_sync(0xFFFFFFFFu, c.x, s + 1)));
                    const unsigned long long a2 = dup2(__int_as_float(__shfl_sync(0xFFFFFFFFu, c.x, s + 2)));
                    const unsigned long long a3 = dup2(__int_as_float(__shfl_sync(0xFFFFFFFFu, c.x, s + 3)));
                    const int k0 = __shfl_sync(0xFFFFFFFFu, c.y, s)     - kp0;
                    const int k1 = __shfl_sync(0xFFFFFFFFu, c.y, s + 1) - kp0;
                    const int k2 = __shfl_sync(0xFFFFFFFFu, c.y, s + 2) - kp0;
                    const int k3 = __shfl_sync(0xFFFFFFFFu, c.y, s + 3) - kp0;
                    const ulonglong2 w0 = *(const ulonglong2*)(slab + (k0 << 7) + lane * 4);
                    const ulonglong2 w1 = *(const ulonglong2*)(slab + (k1 << 7) + lane * 4);
                    const ulonglong2 w2 = *(const ulonglong2*)(slab + (k2 << 7) + lane * 4);
                    const ulonglong2 w3 = *(const ulonglong2*)(slab + (k3 << 7) + lane * 4);
                    fma2(acc0[rr], a0, w0.x); fma2(acc1[rr], a0, w0.y);
                    fma2(acc0[rr], a1, w1.x); fma2(acc1[rr], a1, w1.y);
                    fma2(acc0[rr], a2, w2.x); fma2(acc1[rr], a2, w2.y);
                    fma2(acc0[rr], a3, w3.x); fma2(acc1[rr], a3, w3.y);
                }
                for (; j < je; ++j) {
                    const int s = j - cb;
                    const unsigned long long a = dup2(__int_as_float(__shfl_sync(0xFFFFFFFFu, c.x, s)));
                    const int k = __shfl_sync(0xFFFFFFFFu, c.y, s) - kp0;
                    const ulonglong2 w = *(const ulonglong2*)(slab + (k << 7) + lane * 4);
                    fma2(acc0[rr], a, w.x); fma2(acc1[rr], a, w.y);
                }
            }
            b0c = b0n; b1c = b1n; cc = cn;
        }
    }

    // epilogue
    #pragma unroll
    for (int rr = 0; rr < 8; ++rr) {
        const int row = row0 + rr;
        float v0, v1, v2, v3;
        unpack2(acc0[rr], v0, v1);
        unpack2(acc1[rr], v2, v3);
        if (!BOUND_N || nl + 4 <= N) {
            const float4 bv = *(const float4*)(bias + nl);
            float4 o;
            o.x = v0 + bv.x; o.y = v1 + bv.y; o.z = v2 + bv.z; o.w = v3 + bv.w;
            *(float4*)(C + (size_t)row * N + nl) = o;
        } else {
            const float vv[4] = {v0, v1, v2, v3};
            #pragma unroll
            for (int i = 0; i < 4; ++i)
                if (nl + i < N) C[(size_t)row * N + nl + i] = vv[i] + bias[nl + i];
        }
    }
}

// ================= launch =================
extern "C" void kernel_launch(void* const* d_in, const int* in_sizes, int n_in,
                              void* d_out, int out_size)
{
    const float* x  = (const float*)d_in[0];
    const float* W0 = (const float*)d_in[1];
    const float* b0 = (const float*)d_in[2];
    const float* W1 = (const float*)d_in[3];
    const float* b1 = (const float*)d_in[4];
    const float* Wc = (const float*)d_in[5];
    const float* bc = (const float*)d_in[6];
    float* out = (float*)d_out;

    float *f, *w1t, *wct;
    int2* cp;
    short* bnd;
    cudaGetSymbolAddress((void**)&f,   g_f);
    cudaGetSymbolAddress((void**)&w1t, g_w1t);
    cudaGetSymbolAddress((void**)&wct, g_wct);
    cudaGetSymbolAddress((void**)&cp,  g_cp);
    cudaGetSymbolAddress((void**)&bnd, g_bnd);

    cudaFuncSetAttribute(sparse_gemm5_kernel<false>,
                         cudaFuncAttributeMaxDynamicSharedMemorySize, SLAB5_BYTES);
    cudaFuncSetAttribute(sparse_gemm5_kernel<true>,
                         cudaFuncAttributeMaxDynamicSharedMemorySize, SLAB5_BYTES);

    const dim3 blk(256);

    // weight transposes
    transpose_kernel<<<dim3(H_DIM / 32, H_DIM / 32), dim3(32, 8)>>>(W1, w1t, H_DIM, H_DIM);
    transpose_kernel<<<dim3(H_DIM / 32, (NC_DIM + 31) / 32), dim3(32, 8)>>>(Wc, wct, NC_DIM, H_DIM);

    // Layer 0 (dense, proven)
    gemm_nt_kernel<<<dim3(H_DIM / 128, B_ROWS / 128), blk>>>(x, W0, b0, f, H_DIM, IN_DIM);
    topk_relu_compact_kernel<<<B_ROWS, blk>>>(f, cp, bnd);

    // Layer 1 (sparse v5)
    sparse_gemm5_kernel<false><<<dim3(H_DIM / NT, B_ROWS / 64), blk, SLAB5_BYTES>>>(
        cp, bnd, w1t, b1, f, H_DIM);
    topk_relu_compact_kernel<<<B_ROWS, blk>>>(f, cp, bnd);

    // Classifier (sparse v5, N=1000)
    sparse_gemm5_kernel<true><<<dim3((NC_DIM + NT - 1) / NT, B_ROWS / 64), blk, SLAB5_BYTES>>>(
        cp, bnd, wct, bc, out, NC_DIM);
}